// round 15
// baseline (speedup 1.0000x reference)
#include <cuda_runtime.h>

// out[b, idx] = prod_w ( bit_{19-w}(idx) ? sin(h[b,w]) : cos(h[b,w]) ),
// h = (x + params) * 0.5. Wire w maps to idx bit (19-w).
//
// Experiment (re-submit after infra failure): setup-per-byte at fixed
// granularity. 16384 CTAs (256 x 64 batches), 128 threads/CTA, 4 hi-rows
// (16 KB) per CTA — same chunking as the 40.9 us R7 winner, but half the
// threads -> half the setup instructions per byte; each thread stores
// 8 float4 = 128 B with 8-deep independent store MLP.
// Thread's float4 index p = i*128 + tid (i=0..7): hi row = i>>1, lo bit9 = i&1,
// lo bits 2..8 = tid bits 0..6 -> wires 17..11, j bits 0..1 -> wires 19,18.

#define N_WIRES 20
#define BATCH 64
#define THREADS 128

__global__ __launch_bounds__(THREADS, 16)
void qansatz_kernel(const float* __restrict__ x,
                    const float* __restrict__ params,
                    float* __restrict__ out)
{
    __shared__ float sc[N_WIRES];
    __shared__ float ss[N_WIRES];

    const int b   = blockIdx.y;          // batch
    const int bx  = blockIdx.x;          // hi_base = 4*bx, bx in [0,256)
    const int tid = threadIdx.x;         // 0..127

    // 1) cos/sin for this batch's 20 wires (one barrier)
    if (tid < N_WIRES) {
        float h = (x[b * N_WIRES + tid] + params[tid]) * 0.5f;
        float c, s;
        sincosf(h, &s, &c);
        sc[tid] = c;
        ss[tid] = s;
    }
    __syncthreads();

    // 2) lo common: lo bits 2..8 come from tid bits 0..6 -> wires 17..11.
    float lo_common = 1.0f;
    #pragma unroll
    for (int q = 2; q < 9; q++)
        lo_common *= ((tid >> (q - 2)) & 1) ? ss[19 - q] : sc[19 - q];

    // j bit0 -> wire 19, j bit1 -> wire 18
    float lv0 = sc[19] * sc[18];
    float lv1 = ss[19] * sc[18];
    float lv2 = sc[19] * ss[18];
    float lv3 = ss[19] * ss[18];

    // 3) hi common: hi = 4*bx + r; hi bits 2..9 = bx bits 0..7 -> wires 7..0.
    float hi_common = 1.0f;
    #pragma unroll
    for (int q = 2; q < 10; q++)
        hi_common *= ((bx >> (q - 2)) & 1) ? ss[9 - q] : sc[9 - q];

    // r bit0 -> wire 9, r bit1 -> wire 8
    float hv[4];
    hv[0] = sc[9] * sc[8];
    hv[1] = ss[9] * sc[8];
    hv[2] = sc[9] * ss[8];
    hv[3] = ss[9] * ss[8];

    // lo bit 9 -> wire 10
    float f9c = sc[10], f9s = ss[10];

    float base = lo_common * hi_common;
    float c0 = base * lv0, c1 = base * lv1, c2 = base * lv2, c3 = base * lv3;

    // per-iteration scalar: ph[i] = hv[i>>1] * (i&1 ? f9s : f9c)
    float ph[8];
    #pragma unroll
    for (int r = 0; r < 4; r++) {
        ph[2 * r]     = hv[r] * f9c;
        ph[2 * r + 1] = hv[r] * f9s;
    }

    // 4) stream out: 8 independent float4 stores per thread, fully coalesced.
    //    CTA covers 8 * 128 * 4 = 4096 floats = 16 KB = 4 hi-rows.
    size_t off = ((size_t)b << 20) + ((size_t)bx << 12);
    float4* dst = reinterpret_cast<float4*>(out + off) + tid;

    #pragma unroll
    for (int i = 0; i < 8; i++) {
        float p = ph[i];
        float4 v;
        v.x = p * c0;
        v.y = p * c1;
        v.z = p * c2;
        v.w = p * c3;
        __stcs(dst + i * 128, v);    // streaming store: write-once output
    }
}

extern "C" void kernel_launch(void* const* d_in, const int* in_sizes, int n_in,
                              void* d_out, int out_size)
{
    const float* x      = (const float*)d_in[0];   // (64, 20)
    const float* params = (const float*)d_in[1];   // (20,)
    float* out          = (float*)d_out;           // (64, 2^20)

    dim3 grid(256, BATCH);                         // 16384 CTAs, 16 KB each
    qansatz_kernel<<<grid, THREADS>>>(x, params, out);
}